// round 2
// baseline (speedup 1.0000x reference)
#include <cuda_runtime.h>
#include <cstdint>

#define NV 100000
#define NE 800000
#define D  256

// Scratch accumulator for scatter-sum (allocation-free: __device__ global).
__device__ __align__(16) float g_aggr[(size_t)NV * D];

// Flag: 1 if edge_index buffer is really int64, 0 if int32 (jnp.int64 w/o x64).
__device__ int g_idx_is64;

// ---------------------------------------------------------------------------
// Kernel 0: detect edge_index dtype. Indices < 2^17, so if buffer is int64
// every high-32 word is 0. If int32, "high words" are random indices
// (nonzero w.p. ~1-1e-5 each); checking 64 makes misdetection impossible.
// ---------------------------------------------------------------------------
__global__ void detect_idx_kernel(const int* __restrict__ idx_raw) {
    int is64 = 1;
#pragma unroll 1
    for (int i = 0; i < 64; i++)
        if (idx_raw[2 * i + 1] != 0) { is64 = 0; break; }
    g_idx_is64 = is64;
}

// ---------------------------------------------------------------------------
// Kernel 1: zero the aggregation buffer (exact cover: NV*D/4 float4 = 6.4M)
// ---------------------------------------------------------------------------
__global__ void zero_aggr_kernel() {
    size_t i = (size_t)blockIdx.x * blockDim.x + threadIdx.x;
    ((float4*)g_aggr)[i] = make_float4(0.f, 0.f, 0.f, 0.f);
}

// ---------------------------------------------------------------------------
// Kernel 2: scatter-add edge features onto receiver vertices.
// One warp per edge; 64 x red.global.add.v4.f32 per edge (2 per lane).
// ---------------------------------------------------------------------------
__global__ void scatter_kernel(const float* __restrict__ efeat,
                               const void* __restrict__ eidx_raw) {
    int e    = blockIdx.x * 8 + (threadIdx.x >> 5);   // 100000 blocks x 8 warps
    int lane = threadIdx.x & 31;

    long long r;
    if (g_idx_is64) r = ((const long long*)eidx_raw)[NE + e];  // row 1 = receivers
    else            r = ((const int*)eidx_raw)[NE + e];
    if (r < 0 || r >= NV) return;                      // safety: never trap

    const float4* src = (const float4*)(efeat + (size_t)e * D);
    float* dst = g_aggr + (size_t)r * D;
#pragma unroll
    for (int i = 0; i < 2; i++) {
        int c = lane + i * 32;                         // float4 index 0..63
        float4 v = src[c];
        asm volatile("red.global.add.v4.f32 [%0], {%1,%2,%3,%4};"
                     :: "l"(dst + c * 4), "f"(v.x), "f"(v.y), "f"(v.z), "f"(v.w)
                     : "memory");
    }
}

// ---------------------------------------------------------------------------
// Kernel 3: fused 3-layer MLP on [vertex | aggr]  (K=512 -> 256 -> 256)
// CTA tile: 64 rows x 256 cols. 256 threads, 8x8 outputs/thread.
// Accumulators in packed f32x2 (fma.rn.f32x2: 2 FMA per fp-pipe issue).
// ---------------------------------------------------------------------------
#define BM   64
#define BK   16
#define XPAD 20                            // 20 floats = 80B, keeps float4 alignment
#define SMEM_FLOATS (BM * D + BM * XPAD + BK * D)
#define SMEM_BYTES  (SMEM_FLOATS * 4)

__device__ __forceinline__ unsigned long long pack2(float x) {
    unsigned long long r; unsigned u = __float_as_uint(x);
    asm("mov.b64 %0, {%1, %1};" : "=l"(r) : "r"(u));
    return r;
}
#define FMA2(d, a, b) asm("fma.rn.f32x2 %0, %1, %2, %0;" : "+l"(d) : "l"(a), "l"(b))

__device__ __forceinline__ void unpack2(unsigned long long v, float& lo, float& hi) {
    unsigned a, b;
    asm("mov.b64 {%0, %1}, %2;" : "=r"(a), "=r"(b) : "l"(v));
    lo = __uint_as_float(a); hi = __uint_as_float(b);
}

__global__ __launch_bounds__(256, 2)
void mlp_kernel(const float* __restrict__ vfeat,
                const float* __restrict__ W1, const float* __restrict__ b1,
                const float* __restrict__ W2, const float* __restrict__ b2,
                const float* __restrict__ W3, const float* __restrict__ b3,
                float* __restrict__ out)
{
    extern __shared__ float sm[];
    float* h_buf = sm;                   // BM * D      (64 KB)  intermediate activations
    float* Xs    = h_buf + BM * D;       // BM * XPAD   (5 KB)   layer-1 input stage
    float* Ws    = Xs + BM * XPAD;       // BK * D      (16 KB)  weight stage

    const int tid  = threadIdx.x;
    const int tcol = tid & 31;           // 32 col-groups of 8
    const int trow = tid >> 5;           // 8 row-groups of 8
    const int row0 = blockIdx.x * BM;

    unsigned long long acc[8][4];

    // ================= Layer 1: X=[vertex|aggr] (K=512) @ W1, ReLU =========
#pragma unroll
    for (int i = 0; i < 8; i++)
#pragma unroll
        for (int j = 0; j < 4; j++) acc[i][j] = 0ULL;

    for (int k0 = 0; k0 < 2 * D; k0 += BK) {
        const float* src = (k0 < D) ? (vfeat  + (size_t)row0 * D + k0)
                                    : (g_aggr + (size_t)row0 * D + (k0 - D));
        {   // stage X: 64 rows x 16 cols -> 256 float4 chunks, 1 per thread
            int r  = tid >> 2;
            int c4 = (tid & 3) * 4;
            float4 v = make_float4(0.f, 0.f, 0.f, 0.f);
            if (row0 + r < NV) v = *(const float4*)(src + (size_t)r * D + c4);
            *(float4*)(Xs + r * XPAD + c4) = v;
        }
        {   // stage W: contiguous 16*256 floats = 1024 float4, 4 per thread
            const float4* wsrc = (const float4*)(W1 + (size_t)k0 * D);
            float4* wdst = (float4*)Ws;
#pragma unroll
            for (int i = 0; i < 4; i++) wdst[tid + i * 256] = wsrc[tid + i * 256];
        }
        __syncthreads();
#pragma unroll
        for (int kk = 0; kk < BK; kk++) {
            const float* wrow = Ws + kk * D + tcol * 8;
            ulonglong2 q0 = *(const ulonglong2*)wrow;
            ulonglong2 q1 = *(const ulonglong2*)(wrow + 4);
            unsigned long long bb[4] = {q0.x, q0.y, q1.x, q1.y};
#pragma unroll
            for (int i = 0; i < 8; i++) {
                unsigned long long a2 = pack2(Xs[(trow * 8 + i) * XPAD + kk]);
#pragma unroll
                for (int j = 0; j < 4; j++) FMA2(acc[i][j], a2, bb[j]);
            }
        }
        __syncthreads();
    }
    {   // bias + ReLU -> h_buf
        float4 bv0 = *(const float4*)(b1 + tcol * 8);
        float4 bv1 = *(const float4*)(b1 + tcol * 8 + 4);
        float bias[8] = {bv0.x, bv0.y, bv0.z, bv0.w, bv1.x, bv1.y, bv1.z, bv1.w};
#pragma unroll
        for (int i = 0; i < 8; i++) {
            float v[8];
#pragma unroll
            for (int j = 0; j < 4; j++) unpack2(acc[i][j], v[2 * j], v[2 * j + 1]);
#pragma unroll
            for (int j = 0; j < 8; j++) v[j] = fmaxf(v[j] + bias[j], 0.f);
            float* dst = h_buf + (trow * 8 + i) * D + tcol * 8;
            *(float4*)dst       = make_float4(v[0], v[1], v[2], v[3]);
            *(float4*)(dst + 4) = make_float4(v[4], v[5], v[6], v[7]);
        }
    }
    __syncthreads();

    // ================= Layers 2 & 3: h (K=256) @ W, input from smem ========
#pragma unroll 1
    for (int layer = 0; layer < 2; layer++) {
        const float* Wg = (layer == 0) ? W2 : W3;
        const float* bg = (layer == 0) ? b2 : b3;
#pragma unroll
        for (int i = 0; i < 8; i++)
#pragma unroll
            for (int j = 0; j < 4; j++) acc[i][j] = 0ULL;

        for (int k0 = 0; k0 < D; k0 += BK) {
            {   // stage W
                const float4* wsrc = (const float4*)(Wg + (size_t)k0 * D);
                float4* wdst = (float4*)Ws;
#pragma unroll
                for (int i = 0; i < 4; i++) wdst[tid + i * 256] = wsrc[tid + i * 256];
            }
            __syncthreads();
#pragma unroll
            for (int kk = 0; kk < BK; kk++) {
                const float* wrow = Ws + kk * D + tcol * 8;
                ulonglong2 q0 = *(const ulonglong2*)wrow;
                ulonglong2 q1 = *(const ulonglong2*)(wrow + 4);
                unsigned long long bb[4] = {q0.x, q0.y, q1.x, q1.y};
#pragma unroll
                for (int i = 0; i < 8; i++) {
                    unsigned long long a2 = pack2(h_buf[(trow * 8 + i) * D + k0 + kk]);
#pragma unroll
                    for (int j = 0; j < 4; j++) FMA2(acc[i][j], a2, bb[j]);
                }
            }
            __syncthreads();
        }

        float4 bv0 = *(const float4*)(bg + tcol * 8);
        float4 bv1 = *(const float4*)(bg + tcol * 8 + 4);
        float bias[8] = {bv0.x, bv0.y, bv0.z, bv0.w, bv1.x, bv1.y, bv1.z, bv1.w};

        if (layer == 0) {   // ReLU, back to h_buf (all reads done: loop-end barrier)
#pragma unroll
            for (int i = 0; i < 8; i++) {
                float v[8];
#pragma unroll
                for (int j = 0; j < 4; j++) unpack2(acc[i][j], v[2 * j], v[2 * j + 1]);
#pragma unroll
                for (int j = 0; j < 8; j++) v[j] = fmaxf(v[j] + bias[j], 0.f);
                float* dst = h_buf + (trow * 8 + i) * D + tcol * 8;
                *(float4*)dst       = make_float4(v[0], v[1], v[2], v[3]);
                *(float4*)(dst + 4) = make_float4(v[4], v[5], v[6], v[7]);
            }
            __syncthreads();
        } else {            // final: bias only, write to gmem
#pragma unroll
            for (int i = 0; i < 8; i++) {
                int row = row0 + trow * 8 + i;
                if (row < NV) {
                    float v[8];
#pragma unroll
                    for (int j = 0; j < 4; j++) unpack2(acc[i][j], v[2 * j], v[2 * j + 1]);
#pragma unroll
                    for (int j = 0; j < 8; j++) v[j] += bias[j];
                    float* dst = out + (size_t)row * D + tcol * 8;
                    *(float4*)dst       = make_float4(v[0], v[1], v[2], v[3]);
                    *(float4*)(dst + 4) = make_float4(v[4], v[5], v[6], v[7]);
                }
            }
        }
    }
}

// ---------------------------------------------------------------------------
extern "C" void kernel_launch(void* const* d_in, const int* in_sizes, int n_in,
                              void* d_out, int out_size) {
    const float* vfeat = (const float*)d_in[0];
    const float* efeat = (const float*)d_in[1];
    const void*  eidx  = d_in[2];                        // [2, NE] int64 OR int32
    const float* W1 = (const float*)d_in[3];
    const float* b1 = (const float*)d_in[4];
    const float* W2 = (const float*)d_in[5];
    const float* b2 = (const float*)d_in[6];
    const float* W3 = (const float*)d_in[7];
    const float* b3 = (const float*)d_in[8];
    float* out = (float*)d_out;

    // idempotent; not a stream op, safe under graph capture
    cudaFuncSetAttribute(mlp_kernel, cudaFuncAttributeMaxDynamicSharedMemorySize,
                         SMEM_BYTES);

    detect_idx_kernel<<<1, 1>>>((const int*)eidx);
    zero_aggr_kernel<<<(NV * D / 4) / 256, 256>>>();
    scatter_kernel<<<NE / 8, 256>>>(efeat, eidx);
    mlp_kernel<<<(NV + BM - 1) / BM, 256, SMEM_BYTES>>>(vfeat, W1, b1, W2, b2,
                                                        W3, b3, out);
}